// round 12
// baseline (speedup 1.0000x reference)
#include <cuda_runtime.h>
#include <cuda_bf16.h>
#include <cuda_fp8.h>
#include <math.h>
#include <stdint.h>

#define L_LAYERS 4
#define T_SEQ    4096
#define DM       2048
#define DH       1024
#define KQ       4096        // fp8 K in bytes = 2*DM
#define KU       2048        // fp8 K in b16 units
#define BN_EPS   1e-5f

// scan chunking
#define SCH  64
#define SCHL (T_SEQ / SCH)   // 64

// ---------------------------------------------------------------------------
// Scratch (no cudaMalloc allowed)
// ---------------------------------------------------------------------------
__device__ float g_x [T_SEQ * DM];
__device__ float g_t1[T_SEQ * DM];
__device__ float g_u [T_SEQ * DM];
__device__ float g_v [T_SEQ * DM];
__device__ __nv_bfloat16 g_corr [T_SEQ * DM];            // bf16 correction
__device__ __nv_bfloat16 g_corr2[T_SEQ * DM];
__device__ __nv_bfloat16 g_ah[(size_t)T_SEQ * DM];       // act hi (bf16)
__device__ uint8_t       g_aq[(size_t)T_SEQ * KQ];       // act fp8 interleaved [hi4|lo4]
__device__ __nv_bfloat16 g_wh[2 * (size_t)DM * DM];      // weight hi (bf16), 2 slots
__device__ uint8_t       g_wq[2 * (size_t)DM * KQ];      // wt fp8 interleaved [lo4|hi4]
__device__ float g_mean[DM], g_var[DM];
__device__ float g_bnp[8][2][DM];
__device__ float g_carr[SCH * DH], g_cari[SCH * DH];
__device__ float g_cinr[SCH * DH], g_cini[SCH * DH];

// ---------------------------------------------------------------------------
// PTX helpers
// ---------------------------------------------------------------------------
__device__ __forceinline__ void cp16(uint32_t saddr, const void* g) {
    asm volatile("cp.async.cg.shared.global [%0], [%1], 16;\n" :: "r"(saddr), "l"(g));
}
__device__ __forceinline__ void cp_commit() {
    asm volatile("cp.async.commit_group;\n");
}
template<int N> __device__ __forceinline__ void cp_wait() {
    asm volatile("cp.async.wait_group %0;\n" :: "n"(N));
}
__device__ __forceinline__ void ldsm_x4(uint32_t* r, uint32_t addr) {
    asm volatile("ldmatrix.sync.aligned.m8n8.x4.shared.b16 {%0,%1,%2,%3}, [%4];\n"
                 : "=r"(r[0]), "=r"(r[1]), "=r"(r[2]), "=r"(r[3]) : "r"(addr));
}
__device__ __forceinline__ void mma_bf16(float* c, const uint32_t* a, uint32_t b0, uint32_t b1) {
    asm volatile("mma.sync.aligned.m16n8k16.row.col.f32.bf16.bf16.f32 "
                 "{%0,%1,%2,%3}, {%4,%5,%6,%7}, {%8,%9}, {%0,%1,%2,%3};\n"
                 : "+f"(c[0]), "+f"(c[1]), "+f"(c[2]), "+f"(c[3])
                 : "r"(a[0]), "r"(a[1]), "r"(a[2]), "r"(a[3]), "r"(b0), "r"(b1));
}
__device__ __forceinline__ void mma_e4m3f(float* c, const uint32_t* a, uint32_t b0, uint32_t b1) {
    asm volatile("mma.sync.aligned.m16n8k32.row.col.f32.e4m3.e4m3.f32 "
                 "{%0,%1,%2,%3}, {%4,%5,%6,%7}, {%8,%9}, {%0,%1,%2,%3};\n"
                 : "+f"(c[0]), "+f"(c[1]), "+f"(c[2]), "+f"(c[3])
                 : "r"(a[0]), "r"(a[1]), "r"(a[2]), "r"(a[3]), "r"(b0), "r"(b1));
}

// ---------------------------------------------------------------------------
// Shared GEMM geometry: BM=BN=128, 256 thr, 8 warps of 64x32, 4 stages.
// (R9-proven configuration: regs=128, 2 CTAs/SM, 117us — do not perturb.)
// ---------------------------------------------------------------------------
#define STAGES 4
#define BK 32
#define PADK 40
#define STAGE_BYTES (2 * 128 * PADK * 2)     // 20480
#define KITERS (DM / BK)                     // 64

// ---------------------------------------------------------------------------
// bf16 main GEMM (NT): C = A * B^T + corr(bf16) + bias; z selects slot.
// ---------------------------------------------------------------------------
__global__ __launch_bounds__(256, 2) void gemm_bf16(
    const __nv_bfloat16* __restrict__ A, const __nv_bfloat16* __restrict__ Bbase,
    const float* __restrict__ bias0, const float* __restrict__ bias1,
    const __nv_bfloat16* __restrict__ corr0, const __nv_bfloat16* __restrict__ corr1,
    float* __restrict__ C0, float* __restrict__ C1)
{
    extern __shared__ __nv_bfloat16 sh[];
    const int z = blockIdx.z;
    const __nv_bfloat16* B = Bbase + (size_t)z * DM * DM;
    const float* bias = z ? bias1 : bias0;
    const __nv_bfloat16* corr = z ? corr1 : corr0;
    float* C = z ? C1 : C0;

    const int bm = blockIdx.y * 128, bn = blockIdx.x * 128;
    const int tid = threadIdx.x, lane = tid & 31, warp = tid >> 5;
    const int wm = (warp >> 2) * 64, wn = (warp & 3) * 32;

    uint32_t sbase = (uint32_t)__cvta_generic_to_shared(sh);

    const int r0 = tid >> 2, seg = (tid & 3) * 8;
    uint32_t dA0 = sbase + (r0 * PADK + seg) * 2;
    uint32_t dA1 = sbase + ((r0 + 64) * PADK + seg) * 2;
    uint32_t dB0 = sbase + (128 * PADK + r0 * PADK + seg) * 2;
    uint32_t dB1 = dB0 + 64 * PADK * 2;
    const __nv_bfloat16* gA0 = A + (size_t)(bm + r0) * DM + seg;
    const __nv_bfloat16* gA1 = A + (size_t)(bm + r0 + 64) * DM + seg;
    const __nv_bfloat16* gB0 = B + (size_t)(bn + r0) * DM + seg;
    const __nv_bfloat16* gB1 = B + (size_t)(bn + r0 + 64) * DM + seg;

    uint32_t aoff[4], boff[2];
    #pragma unroll
    for (int mi = 0; mi < 4; mi++)
        aoff[mi] = ((wm + mi * 16 + (lane & 15)) * PADK + (lane >> 4) * 8) * 2;
    #pragma unroll
    for (int nh = 0; nh < 2; nh++)
        boff[nh] = (128 * PADK + (wn + nh * 16 + (lane >> 4) * 8 + (lane & 7)) * PADK
                    + ((lane >> 3) & 1) * 8) * 2;

    float acc[4][4][4] = {};

    auto load_stage = [&](int s) {
        uint32_t so = (uint32_t)(s & (STAGES - 1)) * STAGE_BYTES;
        int k0 = s * BK;
        cp16(dA0 + so, gA0 + k0);
        cp16(dA1 + so, gA1 + k0);
        cp16(dB0 + so, gB0 + k0);
        cp16(dB1 + so, gB1 + k0);
    };

    load_stage(0); cp_commit();
    load_stage(1); cp_commit();
    load_stage(2); cp_commit();

    for (int it = 0; it < KITERS; it++) {
        cp_wait<2>();
        __syncthreads();
        uint32_t sb = sbase + (uint32_t)(it & (STAGES - 1)) * STAGE_BYTES;

        if (it + 3 < KITERS) load_stage(it + 3);
        cp_commit();

        #pragma unroll
        for (int ks = 0; ks < 2; ks++) {
            uint32_t ko = sb + ks * 32;
            uint32_t a[4][4], b[2][4];
            #pragma unroll
            for (int mi = 0; mi < 4; mi++) ldsm_x4(a[mi], ko + aoff[mi]);
            #pragma unroll
            for (int nh = 0; nh < 2; nh++) ldsm_x4(b[nh], ko + boff[nh]);
            #pragma unroll
            for (int mi = 0; mi < 4; mi++)
                #pragma unroll
                for (int ni = 0; ni < 4; ni++)
                    mma_bf16(acc[mi][ni], a[mi], b[ni >> 1][(ni & 1) * 2],
                             b[ni >> 1][(ni & 1) * 2 + 1]);
        }
    }

    const int er = lane >> 2, ec = (lane & 3) * 2;
    #pragma unroll
    for (int mi = 0; mi < 4; mi++) {
        int row = bm + wm + mi * 16 + er;
        #pragma unroll
        for (int ni = 0; ni < 4; ni++) {
            int col = bn + wn + ni * 8 + ec;
            float b0 = 0.f, b1 = 0.f;
            if (bias) { b0 = bias[col]; b1 = bias[col + 1]; }
            __nv_bfloat162 c0 = *(const __nv_bfloat162*)&corr[(size_t)row * DM + col];
            __nv_bfloat162 c1 = *(const __nv_bfloat162*)&corr[(size_t)(row + 8) * DM + col];
            float2 v;
            v.x = acc[mi][ni][0] + b0 + __bfloat162float(c0.x);
            v.y = acc[mi][ni][1] + b1 + __bfloat162float(c0.y);
            *(float2*)&C[(size_t)row * DM + col] = v;
            v.x = acc[mi][ni][2] + b0 + __bfloat162float(c1.x);
            v.y = acc[mi][ni][3] + b1 + __bfloat162float(c1.y);
            *(float2*)&C[(size_t)(row + 8) * DM + col] = v;
        }
    }
}

// ---------------------------------------------------------------------------
// fp8 correction GEMM (NT): corr(bf16) = (A' * B'^T)/256; z selects slot.
// ---------------------------------------------------------------------------
__global__ __launch_bounds__(256, 2) void gemm_fp8(
    const uint16_t* __restrict__ A, const uint16_t* __restrict__ Bbase,
    __nv_bfloat16* __restrict__ C0, __nv_bfloat16* __restrict__ C1)
{
    extern __shared__ __nv_bfloat16 sh[];
    const int z = blockIdx.z;
    const uint16_t* B = Bbase + (size_t)z * DM * KU;
    __nv_bfloat16* C = z ? C1 : C0;

    const int bm = blockIdx.y * 128, bn = blockIdx.x * 128;
    const int tid = threadIdx.x, lane = tid & 31, warp = tid >> 5;
    const int wm = (warp >> 2) * 64, wn = (warp & 3) * 32;

    uint32_t sbase = (uint32_t)__cvta_generic_to_shared(sh);

    const int r0 = tid >> 2, seg = (tid & 3) * 8;
    uint32_t dA0 = sbase + (r0 * PADK + seg) * 2;
    uint32_t dA1 = sbase + ((r0 + 64) * PADK + seg) * 2;
    uint32_t dB0 = sbase + (128 * PADK + r0 * PADK + seg) * 2;
    uint32_t dB1 = dB0 + 64 * PADK * 2;
    const uint16_t* gA0 = A + (size_t)(bm + r0) * KU + seg;
    const uint16_t* gA1 = A + (size_t)(bm + r0 + 64) * KU + seg;
    const uint16_t* gB0 = B + (size_t)(bn + r0) * KU + seg;
    const uint16_t* gB1 = B + (size_t)(bn + r0 + 64) * KU + seg;

    uint32_t aoff[4], boff[2];
    #pragma unroll
    for (int mi = 0; mi < 4; mi++)
        aoff[mi] = ((wm + mi * 16 + (lane & 15)) * PADK + (lane >> 4) * 8) * 2;
    #pragma unroll
    for (int nh = 0; nh < 2; nh++)
        boff[nh] = (128 * PADK + (wn + nh * 16 + (lane >> 4) * 8 + (lane & 7)) * PADK
                    + ((lane >> 3) & 1) * 8) * 2;

    float acc[4][4][4] = {};

    auto load_stage = [&](int s) {
        uint32_t so = (uint32_t)(s & (STAGES - 1)) * STAGE_BYTES;
        int k0 = s * BK;
        cp16(dA0 + so, gA0 + k0);
        cp16(dA1 + so, gA1 + k0);
        cp16(dB0 + so, gB0 + k0);
        cp16(dB1 + so, gB1 + k0);
    };

    load_stage(0); cp_commit();
    load_stage(1); cp_commit();
    load_stage(2); cp_commit();

    for (int it = 0; it < KITERS; it++) {
        cp_wait<2>();
        __syncthreads();
        uint32_t sb = sbase + (uint32_t)(it & (STAGES - 1)) * STAGE_BYTES;

        if (it + 3 < KITERS) load_stage(it + 3);
        cp_commit();

        #pragma unroll
        for (int ks = 0; ks < 2; ks++) {
            uint32_t ko = sb + ks * 32;
            uint32_t a[4][4], b[2][4];
            #pragma unroll
            for (int mi = 0; mi < 4; mi++) ldsm_x4(a[mi], ko + aoff[mi]);
            #pragma unroll
            for (int nh = 0; nh < 2; nh++) ldsm_x4(b[nh], ko + boff[nh]);
            #pragma unroll
            for (int mi = 0; mi < 4; mi++)
                #pragma unroll
                for (int ni = 0; ni < 4; ni++)
                    mma_e4m3f(acc[mi][ni], a[mi], b[ni >> 1][(ni & 1) * 2],
                              b[ni >> 1][(ni & 1) * 2 + 1]);
        }
    }

    const float sc = 1.f / 256.f;
    const int er = lane >> 2, ec = (lane & 3) * 2;
    #pragma unroll
    for (int mi = 0; mi < 4; mi++) {
        int row = bm + wm + mi * 16 + er;
        #pragma unroll
        for (int ni = 0; ni < 4; ni++) {
            int col = bn + wn + ni * 8 + ec;
            __nv_bfloat162 v;
            v = __floats2bfloat162_rn(acc[mi][ni][0] * sc, acc[mi][ni][1] * sc);
            *(__nv_bfloat162*)&C[(size_t)row * DM + col] = v;
            v = __floats2bfloat162_rn(acc[mi][ni][2] * sc, acc[mi][ni][3] * sc);
            *(__nv_bfloat162*)&C[(size_t)(row + 8) * DM + col] = v;
        }
    }
}

// ---------------------------------------------------------------------------
// vectorized emit helpers — interleaved 8B blocks (one store each).
// ---------------------------------------------------------------------------
__device__ __forceinline__ uint32_t e4m3x2(float a, float b) {
    return (uint32_t)__nv_cvt_float2_to_fp8x2(make_float2(a, b), __NV_SATFINITE, __NV_E4M3);
}
__device__ __forceinline__ void emit_act4(float4 v, size_t m, int n4,
                                          __nv_bfloat16* ah, uint8_t* aq) {
    __nv_bfloat162 h01 = __floats2bfloat162_rn(v.x, v.y);
    __nv_bfloat162 h23 = __floats2bfloat162_rn(v.z, v.w);
    uint2 hs;
    hs.x = *(uint32_t*)&h01;
    hs.y = *(uint32_t*)&h23;
    *(uint2*)&ah[m * DM + n4] = hs;
    float l0 = v.x - __bfloat162float(h01.x);
    float l1 = v.y - __bfloat162float(h01.y);
    float l2 = v.z - __bfloat162float(h23.x);
    float l3 = v.w - __bfloat162float(h23.y);
    uint2 q;
    q.x = e4m3x2(v.x, v.y) | (e4m3x2(v.z, v.w) << 16);
    q.y = e4m3x2(l0 * 256.f, l1 * 256.f) | (e4m3x2(l2 * 256.f, l3 * 256.f) << 16);
    *(uint2*)&aq[m * KQ + 2 * n4] = q;
}
__device__ __forceinline__ void emit_wt4(float4 v, size_t n, int k4,
                                         __nv_bfloat16* wh, uint8_t* wq) {
    __nv_bfloat162 h01 = __floats2bfloat162_rn(v.x, v.y);
    __nv_bfloat162 h23 = __floats2bfloat162_rn(v.z, v.w);
    uint2 hs;
    hs.x = *(uint32_t*)&h01;
    hs.y = *(uint32_t*)&h23;
    *(uint2*)&wh[n * DM + k4] = hs;
    float l0 = v.x - __bfloat162float(h01.x);
    float l1 = v.y - __bfloat162float(h01.y);
    float l2 = v.z - __bfloat162float(h23.x);
    float l3 = v.w - __bfloat162float(h23.y);
    uint2 q;
    q.x = e4m3x2(l0 * 256.f, l1 * 256.f) | (e4m3x2(l2 * 256.f, l3 * 256.f) << 16);
    q.y = e4m3x2(v.x, v.y) | (e4m3x2(v.z, v.w) << 16);
    *(uint2*)&wq[n * KQ + 2 * k4] = q;
}

// ---------------------------------------------------------------------------
// BatchNorm (two-phase stats, float4)
// ---------------------------------------------------------------------------
__global__ void bnp1(const float* __restrict__ x)
{
    const int c4 = blockIdx.x * 128 + (threadIdx.x & 31) * 4;
    const int r0 = threadIdx.x >> 5;
    const int t0 = blockIdx.y * 512;
    float4 s = {0,0,0,0}, ss = {0,0,0,0};
    for (int t = t0 + r0; t < t0 + 512; t += 8) {
        float4 v = *(const float4*)&x[(size_t)t * DM + c4];
        s.x += v.x; s.y += v.y; s.z += v.z; s.w += v.w;
        ss.x += v.x*v.x; ss.y += v.y*v.y; ss.z += v.z*v.z; ss.w += v.w*v.w;
    }
    __shared__ float4 sh_s[8][32], sh_ss[8][32];
    sh_s[r0][threadIdx.x & 31]  = s;
    sh_ss[r0][threadIdx.x & 31] = ss;
    __syncthreads();
    if (r0 == 0) {
        for (int r = 1; r < 8; r++) {
            float4 a = sh_s[r][threadIdx.x & 31], b = sh_ss[r][threadIdx.x & 31];
            s.x += a.x; s.y += a.y; s.z += a.z; s.w += a.w;
            ss.x += b.x; ss.y += b.y; ss.z += b.z; ss.w += b.w;
        }
        *(float4*)&g_bnp[blockIdx.y][0][c4] = s;
        *(float4*)&g_bnp[blockIdx.y][1][c4] = ss;
    }
}

__global__ void bnp2()
{
    int col = blockIdx.x * blockDim.x + threadIdx.x;
    float s = 0.f, ss = 0.f;
    #pragma unroll
    for (int r = 0; r < 8; r++) { s += g_bnp[r][0][col]; ss += g_bnp[r][1][col]; }
    float mu = s / (float)T_SEQ;
    g_mean[col] = mu;
    g_var[col]  = ss / (float)T_SEQ - mu * mu;
}

__global__ void bn_fuse(const float* __restrict__ x,
                        __nv_bfloat16* __restrict__ ah, uint8_t* __restrict__ aq,
                        const float* __restrict__ w, const float* __restrict__ b)
{
    int idx = blockIdx.x * blockDim.x + threadIdx.x;     // over T*DM/4
    int n4 = (idx & (DM / 4 - 1)) * 4;
    size_t m = idx >> 9;
    float4 xv = *(const float4*)&x[m * DM + n4];
    float4 mu = *(const float4*)&g_mean[n4];
    float4 va = *(const float4*)&g_var[n4];
    float4 wv = *(const float4*)&w[n4];
    float4 bv = *(const float4*)&b[n4];
    float4 v;
    v.x = (xv.x - mu.x) * rsqrtf(va.x + BN_EPS) * wv.x + bv.x;
    v.y = (xv.y - mu.y) * rsqrtf(va.y + BN_EPS) * wv.y + bv.y;
    v.z = (xv.z - mu.z) * rsqrtf(va.z + BN_EPS) * wv.z + bv.z;
    v.w = (xv.w - mu.w) * rsqrtf(va.w + BN_EPS) * wv.w + bv.w;
    emit_act4(v, m, n4, ah, aq);
}

// ---------------------------------------------------------------------------
// Weight packing (float4)
// ---------------------------------------------------------------------------
__global__ void pack_w_plain(const float* __restrict__ W,
                             __nv_bfloat16* __restrict__ wh, uint8_t* __restrict__ wq)
{
    int idx = blockIdx.x * blockDim.x + threadIdx.x;
    size_t n = idx >> 9;
    int k4 = (idx & (DM / 4 - 1)) * 4;
    float4 v = *(const float4*)&W[n * DM + k4];
    emit_wt4(v, n, k4, wh, wq);
}

__global__ void pack_w_dual(const float* __restrict__ W1, const float* __restrict__ W2,
                            __nv_bfloat16* __restrict__ wh, uint8_t* __restrict__ wq)
{
    int idx = blockIdx.x * blockDim.x + threadIdx.x;
    size_t nn = idx >> 9;
    int slot = (nn >= DM);
    size_t n = nn & (DM - 1);
    int k4 = (idx & (DM / 4 - 1)) * 4;
    const float* W = slot ? W2 : W1;
    float4 v = *(const float4*)&W[n * DM + k4];
    emit_wt4(v, n, k4, wh + (size_t)slot * DM * DM, wq + (size_t)slot * DM * KQ);
}

__global__ void pack_Bn(const float* __restrict__ B_re, const float* __restrict__ B_im,
                        const float* __restrict__ gamma_log,
                        __nv_bfloat16* __restrict__ wh, uint8_t* __restrict__ wq)
{
    int idx = blockIdx.x * blockDim.x + threadIdx.x;
    size_t n = idx >> 9;
    int k4 = (idx & (DM / 4 - 1)) * 4;
    int jj = (int)n & (DH - 1);
    float g = expf(gamma_log[jj]);
    const float* src = (n < DH) ? B_re : B_im;
    float4 v = *(const float4*)&src[(size_t)jj * DM + k4];
    v.x *= g; v.y *= g; v.z *= g; v.w *= g;
    emit_wt4(v, n, k4, wh, wq);
}

__global__ void pack_Cc(const float* __restrict__ C_re, const float* __restrict__ C_im,
                        __nv_bfloat16* __restrict__ wh, uint8_t* __restrict__ wq)
{
    int idx = blockIdx.x * blockDim.x + threadIdx.x;
    size_t n = idx >> 9;
    int k4 = (idx & (DM / 4 - 1)) * 4;
    float4 v;
    if (k4 < DH) {
        v = *(const float4*)&C_re[n * DH + k4];
    } else {
        v = *(const float4*)&C_im[n * DH + (k4 - DH)];
        v.x = -v.x; v.y = -v.y; v.z = -v.z; v.w = -v.w;
    }
    emit_wt4(v, n, k4, wh, wq);
}

__global__ void pack_act_plain(const float* __restrict__ X,
                               __nv_bfloat16* __restrict__ ah, uint8_t* __restrict__ aq)
{
    int idx = blockIdx.x * blockDim.x + threadIdx.x;
    int n4 = (idx & (DM / 4 - 1)) * 4;
    size_t m = idx >> 9;
    float4 v = *(const float4*)&X[m * DM + n4];
    emit_act4(v, m, n4, ah, aq);
}

// ---------------------------------------------------------------------------
// LRU scan — chunk-parallel (3 passes), 4-wide over channels
// ---------------------------------------------------------------------------
__device__ __forceinline__ void lam_of(int j, const float* nu_log, const float* th_log,
                                       float& lr, float& li)
{
    float mag = expf(-expf(nu_log[j]));
    float ph  = expf(th_log[j]);
    lr = mag * cosf(ph);
    li = mag * sinf(ph);
}

__global__ void scan_p1(const float* __restrict__ Bu,
                        const float* __restrict__ nu_log, const float* __restrict__ th_log)
{
    int idx = blockIdx.x * blockDim.x + threadIdx.x;
    int j = (idx & (DH / 4 - 1)) * 4;
    int c = idx >> 8;
    float lr[4], li[4], hr[4] = {}, hi[4] = {};
    #pragma unroll
    for (int q = 0; q < 4; q++) lam_of(j + q, nu_log, th_log, lr[q], li[q]);
    int t0 = c * SCHL;
    for (int t = t0; t < t0 + SCHL; t++) {
        float4 br = *(const float4*)&Bu[(size_t)t * DM + j];
        float4 bi = *(const float4*)&Bu[(size_t)t * DM + DH + j];
        const float brr[4] = {br.x, br.y, br.z, br.w};
        const float bii[4] = {bi.x, bi.y, bi.z, bi.w};
        #pragma unroll
        for (int q = 0; q < 4; q++) {
            float nr = lr[q] * hr[q] - li[q] * hi[q] + brr[q];
            float ni = lr[q] * hi[q] + li[q] * hr[q] + bii[q];
            hr[q] = nr; hi[q] = ni;
        }
    }
    *(float4*)&g_carr[c * DH + j] = make_float4(hr[0], hr[1], hr[2], hr[3]);
    *(float4*)&g_cari[c * DH + j] = make_float4(hi[0], hi[1], hi[2], hi[3]);
}

__global__ void scan_fix(const float* __restrict__ nu_log, const float* __restrict__ th_log)
{
    int j = blockIdx.x * blockDim.x + threadIdx.x;
    float lr, li; lam_of(j, nu_log, th_log, lr, li);
    float ar = lr, ai = li;
    #pragma unroll
    for (int s = 0; s < 6; s++) {       // lam^64
        float nr = ar * ar - ai * ai;
        float ni = 2.f * ar * ai;
        ar = nr; ai = ni;
    }
    float cr = 0.f, ci = 0.f;
    for (int c = 0; c < SCH; c++) {
        g_cinr[c * DH + j] = cr;
        g_cini[c * DH + j] = ci;
        float nr = ar * cr - ai * ci + g_carr[c * DH + j];
        float ni = ar * ci + ai * cr + g_cari[c * DH + j];
        cr = nr; ci = ni;
    }
}

__global__ void scan_p2(const float* __restrict__ Bu,
                        __nv_bfloat16* __restrict__ ah, uint8_t* __restrict__ aq,
                        const float* __restrict__ nu_log, const float* __restrict__ th_log)
{
    int idx = blockIdx.x * blockDim.x + threadIdx.x;
    int j = (idx & (DH / 4 - 1)) * 4;
    int c = idx >> 8;
    float lr[4], li[4], hr[4], hi[4];
    #pragma unroll
    for (int q = 0; q < 4; q++) {
        lam_of(j + q, nu_log, th_log, lr[q], li[q]);
        hr[q] = g_cinr[c * DH + j + q];
        hi[q] = g_cini[c * DH + j + q];
    }
    int t0 = c * SCHL;
    for (int t = t0; t < t0 + SCHL; t++) {
        float4 br = *(const float4*)&Bu[(size_t)t * DM + j];
        float4 bi = *(const float4*)&Bu[(size_t)t * DM + DH + j];
        const float brr[4] = {br.x, br.y, br.z, br.w};
        const float bii[4] = {bi.x, bi.y, bi.z, bi.w};
        #pragma unroll
        for (int q = 0; q < 4; q++) {
            float nr = lr[q] * hr[q] - li[q] * hi[q] + brr[q];
            float ni = lr[q] * hi[q] + li[q] * hr[q] + bii[q];
            hr[q] = nr; hi[q] = ni;
        }
        emit_act4(make_float4(hr[0], hr[1], hr[2], hr[3]), (size_t)t, j, ah, aq);
        emit_act4(make_float4(hi[0], hi[1], hi[2], hi[3]), (size_t)t, DH + j, ah, aq);
    }
}

// ---------------------------------------------------------------------------
// Epilogues
// ---------------------------------------------------------------------------
__global__ void posty_fuse(const float* __restrict__ y, const float* __restrict__ x,
                           const float* __restrict__ Dv,
                           const float* __restrict__ w, const float* __restrict__ b,
                           __nv_bfloat16* __restrict__ ah, uint8_t* __restrict__ aq)
{
    int idx = blockIdx.x * blockDim.x + threadIdx.x;
    int n4 = (idx & (DM / 4 - 1)) * 4;
    size_t m = idx >> 9;
    float4 yv = *(const float4*)&y[m * DM + n4];
    float4 xv = *(const float4*)&x[m * DM + n4];
    float4 mu = *(const float4*)&g_mean[n4];
    float4 va = *(const float4*)&g_var[n4];
    float4 wv = *(const float4*)&w[n4];
    float4 bv = *(const float4*)&b[n4];
    float4 dv = *(const float4*)&Dv[n4];
    float xn0 = (xv.x - mu.x) * rsqrtf(va.x + BN_EPS) * wv.x + bv.x;
    float xn1 = (xv.y - mu.y) * rsqrtf(va.y + BN_EPS) * wv.y + bv.y;
    float xn2 = (xv.z - mu.z) * rsqrtf(va.z + BN_EPS) * wv.z + bv.z;
    float xn3 = (xv.w - mu.w) * rsqrtf(va.w + BN_EPS) * wv.w + bv.w;
    float v0 = yv.x + xn0 * dv.x;
    float v1 = yv.y + xn1 * dv.y;
    float v2 = yv.z + xn2 * dv.z;
    float v3 = yv.w + xn3 * dv.w;
    const float is2 = 0.70710678118654752f;
    float4 g;
    g.x = 0.5f * v0 * (1.f + erff(v0 * is2));
    g.y = 0.5f * v1 * (1.f + erff(v1 * is2));
    g.z = 0.5f * v2 * (1.f + erff(v2 * is2));
    g.w = 0.5f * v3 * (1.f + erff(v3 * is2));
    emit_act4(g, m, n4, ah, aq);
}

// glu + next-layer BN stats (bnp1-style tiling, stats of the OUTPUT)
__global__ void glu_stats(const float* __restrict__ x, const float* __restrict__ u,
                          const float* __restrict__ v, float* __restrict__ out)
{
    const int c4 = blockIdx.x * 128 + (threadIdx.x & 31) * 4;
    const int r0 = threadIdx.x >> 5;
    const int t0 = blockIdx.y * 512;
    float4 s = {0,0,0,0}, ss = {0,0,0,0};
    for (int t = t0 + r0; t < t0 + 512; t += 8) {
        size_t off = (size_t)t * DM + c4;
        float4 xv = *(const float4*)&x[off];
        float4 uv = *(const float4*)&u[off];
        float4 vv = *(const float4*)&v[off];
        float4 o;
        o.x = xv.x + uv.x / (1.f + expf(-vv.x));
        o.y = xv.y + uv.y / (1.f + expf(-vv.y));
        o.z = xv.z + uv.z / (1.f + expf(-vv.z));
        o.w = xv.w + uv.w / (1.f + expf(-vv.w));
        *(float4*)&out[off] = o;
        s.x += o.x; s.y += o.y; s.z += o.z; s.w += o.w;
        ss.x += o.x*o.x; ss.y += o.y*o.y; ss.z += o.z*o.z; ss.w += o.w*o.w;
    }
    __shared__ float4 sh_s[8][32], sh_ss[8][32];
    sh_s[r0][threadIdx.x & 31]  = s;
    sh_ss[r0][threadIdx.x & 31] = ss;
    __syncthreads();
    if (r0 == 0) {
        for (int r = 1; r < 8; r++) {
            float4 a = sh_s[r][threadIdx.x & 31], b = sh_ss[r][threadIdx.x & 31];
            s.x += a.x; s.y += a.y; s.z += a.z; s.w += a.w;
            ss.x += b.x; ss.y += b.y; ss.z += b.z; ss.w += b.w;
        }
        *(float4*)&g_bnp[blockIdx.y][0][c4] = s;
        *(float4*)&g_bnp[blockIdx.y][1][c4] = ss;
    }
}

__global__ void glu_combine(const float* __restrict__ x, const float* __restrict__ u,
                            const float* __restrict__ v, float* __restrict__ out)
{
    int idx = blockIdx.x * blockDim.x + threadIdx.x;
    float4 xv = *(const float4*)&x[(size_t)idx * 4];
    float4 uv = *(const float4*)&u[(size_t)idx * 4];
    float4 vv = *(const float4*)&v[(size_t)idx * 4];
    float4 o;
    o.x = xv.x + uv.x / (1.f + expf(-vv.x));
    o.y = xv.y + uv.y / (1.f + expf(-vv.y));
    o.z = xv.z + uv.z / (1.f + expf(-vv.z));
    o.w = xv.w + uv.w / (1.f + expf(-vv.w));
    *(float4*)&out[(size_t)idx * 4] = o;
}

// ---------------------------------------------------------------------------
// Launch
// ---------------------------------------------------------------------------
extern "C" void kernel_launch(void* const* d_in, const int* in_sizes, int n_in,
                              void* d_out, int out_size)
{
    const float* x_in      = (const float*)d_in[0];
    const float* enc_w     = (const float*)d_in[1];
    const float* enc_b     = (const float*)d_in[2];
    const float* nu_log    = (const float*)d_in[3];
    const float* theta_log = (const float*)d_in[4];
    const float* gamma_log = (const float*)d_in[5];
    const float* B_re      = (const float*)d_in[6];
    const float* B_im      = (const float*)d_in[7];
    const float* C_re      = (const float*)d_in[8];
    const float* C_im      = (const float*)d_in[9];
    const float* Dv        = (const float*)d_in[10];
    const float* norm_w    = (const float*)d_in[11];
    const float* norm_b    = (const float*)d_in[12];
    const float* out1_w    = (const float*)d_in[13];
    const float* out1_b    = (const float*)d_in[14];
    const float* out2_w    = (const float*)d_in[15];
    const float* out2_b    = (const float*)d_in[16];
    float* out = (float*)d_out;
    (void)in_sizes; (void)n_in; (void)out_size;

    float *px, *pt1, *pu, *pv;
    __nv_bfloat16 *pcorr, *pcorr2, *pah, *pwh;
    uint8_t *paq, *pwq;
    cudaGetSymbolAddress((void**)&px,     g_x);
    cudaGetSymbolAddress((void**)&pt1,    g_t1);
    cudaGetSymbolAddress((void**)&pu,     g_u);
    cudaGetSymbolAddress((void**)&pv,     g_v);
    cudaGetSymbolAddress((void**)&pcorr,  g_corr);
    cudaGetSymbolAddress((void**)&pcorr2, g_corr2);
    cudaGetSymbolAddress((void**)&pah,    g_ah);
    cudaGetSymbolAddress((void**)&paq,    g_aq);
    cudaGetSymbolAddress((void**)&pwh,    g_wh);
    cudaGetSymbolAddress((void**)&pwq,    g_wq);

    const int SMEM = STAGES * STAGE_BYTES;   // 81920
    cudaFuncSetAttribute(gemm_bf16, cudaFuncAttributeMaxDynamicSharedMemorySize, SMEM);
    cudaFuncSetAttribute(gemm_fp8,  cudaFuncAttributeMaxDynamicSharedMemorySize, SMEM);

    dim3 ggrid (DM / 128, T_SEQ / 128, 1);   // (16, 32, 1)
    dim3 ggrid2(DM / 128, T_SEQ / 128, 2);   // (16, 32, 2)
    const int EW4 = (T_SEQ * DM) / (4 * 256);   // 8192
    const int PW4 = (DM * DM) / (4 * 256);      // 4096
    dim3 bgrid(DM / 128, 8);
    const int SCB = (SCH * DH / 4) / 256;       // 64 blocks
    const uint16_t* paq16 = (const uint16_t*)paq;
    const uint16_t* pwq16 = (const uint16_t*)pwq;

    // Encoder
    pack_act_plain<<<EW4, 256>>>(x_in, pah, paq);
    pack_w_plain<<<PW4, 256>>>(enc_w, pwh, pwq);
    gemm_fp8<<<ggrid, 256, SMEM>>>(paq16, pwq16, pcorr, pcorr);
    gemm_bf16<<<ggrid, 256, SMEM>>>(pah, pwh, enc_b, enc_b, pcorr, pcorr, px, px);
    bnp1<<<bgrid, 256>>>(px);   // layer-0 stats

    for (int l = 0; l < L_LAYERS; l++) {
        const float* nw  = norm_w + l * DM;
        const float* nb  = norm_b + l * DM;
        const float* nu  = nu_log + l * DH;
        const float* th  = theta_log + l * DH;
        const float* gl  = gamma_log + l * DH;
        const float* bre = B_re + (size_t)l * DH * DM;
        const float* bim = B_im + (size_t)l * DH * DM;
        const float* cre = C_re + (size_t)l * DM * DH;
        const float* cim = C_im + (size_t)l * DM * DH;
        const float* dv  = Dv + l * DM;
        const float* w1  = out1_w + (size_t)l * DM * DM;
        const float* b1  = out1_b + l * DM;
        const float* w2  = out2_w + (size_t)l * DM * DM;
        const float* b2  = out2_b + l * DM;

        bnp2<<<DM / 256, 256>>>();            // finalize stats from g_bnp
        bn_fuse<<<EW4, 256>>>(px, pah, paq, nw, nb);

        pack_Bn<<<PW4, 256>>>(bre, bim, gl, pwh, pwq);
        gemm_fp8<<<ggrid, 256, SMEM>>>(paq16, pwq16, pcorr, pcorr);
        gemm_bf16<<<ggrid, 256, SMEM>>>(pah, pwh, nullptr, nullptr, pcorr, pcorr, pt1, pt1);

        scan_p1<<<SCB, 256>>>(pt1, nu, th);
        scan_fix<<<DH / 256, 256>>>(nu, th);
        scan_p2<<<SCB, 256>>>(pt1, pah, paq, nu, th);

        pack_Cc<<<PW4, 256>>>(cre, cim, pwh, pwq);
        gemm_fp8<<<ggrid, 256, SMEM>>>(paq16, pwq16, pcorr, pcorr);
        gemm_bf16<<<ggrid, 256, SMEM>>>(pah, pwh, nullptr, nullptr, pcorr, pcorr, pt1, pt1);

        posty_fuse<<<EW4, 256>>>(pt1, px, dv, nw, nb, pah, paq);

        // GLU: both branches in z-combined launches
        pack_w_dual<<<2 * PW4, 256>>>(w1, w2, pwh, pwq);
        gemm_fp8<<<ggrid2, 256, SMEM>>>(paq16, pwq16, pcorr, pcorr2);
        gemm_bf16<<<ggrid2, 256, SMEM>>>(pah, pwh, b1, b2, pcorr, pcorr2, pu, pv);

        if (l == L_LAYERS - 1) {
            glu_combine<<<EW4, 256>>>(px, pu, pv, out);
        } else {
            glu_stats<<<bgrid, 256>>>(px, pu, pv, px);   // writes next x + its stats
        }
    }
}

// round 13
// speedup vs baseline: 1.0189x; 1.0189x over previous
#include <cuda_runtime.h>
#include <cuda_bf16.h>
#include <cuda_fp8.h>
#include <math.h>
#include <stdint.h>

#define L_LAYERS 4
#define T_SEQ    4096
#define DM       2048
#define DH       1024
#define KQ       4096        // fp8 K in bytes = 2*DM
#define KU       2048        // fp8 K in b16 units
#define BN_EPS   1e-5f

#define SCH  64
#define SCHL (T_SEQ / SCH)   // 64

// ---------------------------------------------------------------------------
// Scratch (no cudaMalloc allowed)
// ---------------------------------------------------------------------------
__device__ float g_x [T_SEQ * DM];
__device__ float g_t1[T_SEQ * DM];
__device__ float g_u [T_SEQ * DM];
__device__ float g_v [T_SEQ * DM];
__device__ __nv_bfloat16 g_corr [T_SEQ * DM];
__device__ __nv_bfloat16 g_corr2[T_SEQ * DM];
__device__ __nv_bfloat16 g_ah [(size_t)T_SEQ * DM];      // act set 1 (bf16 hi)
__device__ uint8_t       g_aq [(size_t)T_SEQ * KQ];      // act set 1 fp8 [hi2|lo2] blocks
__device__ __nv_bfloat16 g_ah2[(size_t)T_SEQ * DM];      // act set 2 (gelu output)
__device__ uint8_t       g_aq2[(size_t)T_SEQ * KQ];
__device__ __nv_bfloat16 g_wh[2 * (size_t)DM * DM];
__device__ uint8_t       g_wq[2 * (size_t)DM * KQ];      // wt fp8 [lo2|hi2] blocks
__device__ float g_mean[DM], g_var[DM];
__device__ float g_bnp[8][2][DM];
__device__ float g_carr[SCH * DH], g_cari[SCH * DH];
__device__ float g_cinr[SCH * DH], g_cini[SCH * DH];

// ---------------------------------------------------------------------------
// PTX helpers
// ---------------------------------------------------------------------------
__device__ __forceinline__ void cp16(uint32_t saddr, const void* g) {
    asm volatile("cp.async.cg.shared.global [%0], [%1], 16;\n" :: "r"(saddr), "l"(g));
}
__device__ __forceinline__ void cp_commit() {
    asm volatile("cp.async.commit_group;\n");
}
template<int N> __device__ __forceinline__ void cp_wait() {
    asm volatile("cp.async.wait_group %0;\n" :: "n"(N));
}
__device__ __forceinline__ void ldsm_x4(uint32_t* r, uint32_t addr) {
    asm volatile("ldmatrix.sync.aligned.m8n8.x4.shared.b16 {%0,%1,%2,%3}, [%4];\n"
                 : "=r"(r[0]), "=r"(r[1]), "=r"(r[2]), "=r"(r[3]) : "r"(addr));
}
__device__ __forceinline__ void mma_bf16(float* c, const uint32_t* a, uint32_t b0, uint32_t b1) {
    asm volatile("mma.sync.aligned.m16n8k16.row.col.f32.bf16.bf16.f32 "
                 "{%0,%1,%2,%3}, {%4,%5,%6,%7}, {%8,%9}, {%0,%1,%2,%3};\n"
                 : "+f"(c[0]), "+f"(c[1]), "+f"(c[2]), "+f"(c[3])
                 : "r"(a[0]), "r"(a[1]), "r"(a[2]), "r"(a[3]), "r"(b0), "r"(b1));
}
__device__ __forceinline__ void mma_e4m3f(float* c, const uint32_t* a, uint32_t b0, uint32_t b1) {
    asm volatile("mma.sync.aligned.m16n8k32.row.col.f32.e4m3.e4m3.f32 "
                 "{%0,%1,%2,%3}, {%4,%5,%6,%7}, {%8,%9}, {%0,%1,%2,%3};\n"
                 : "+f"(c[0]), "+f"(c[1]), "+f"(c[2]), "+f"(c[3])
                 : "r"(a[0]), "r"(a[1]), "r"(a[2]), "r"(a[3]), "r"(b0), "r"(b1));
}

// fp8 helpers — granularity-2 interleave
__device__ __forceinline__ uint32_t e4m3x2(float a, float b) {
    return (uint32_t)__nv_cvt_float2_to_fp8x2(make_float2(a, b), __NV_SATFINITE, __NV_E4M3);
}
// emit 2 consecutive activation elements (bf16 hi + fp8 block [hi2|lo2])
__device__ __forceinline__ void emit_act2(float g0, float g1, size_t m, int n2,
                                          __nv_bfloat16* ah, uint8_t* aq) {
    __nv_bfloat162 h = __floats2bfloat162_rn(g0, g1);
    *(__nv_bfloat162*)&ah[m * DM + n2] = h;
    float l0 = g0 - __bfloat162float(h.x);
    float l1 = g1 - __bfloat162float(h.y);
    uint32_t q = e4m3x2(g0, g1) | (e4m3x2(l0 * 256.f, l1 * 256.f) << 16);
    *(uint32_t*)&aq[m * KQ + 2 * n2] = q;
}
__device__ __forceinline__ void emit_act4(float4 v, size_t m, int n4,
                                          __nv_bfloat16* ah, uint8_t* aq) {
    __nv_bfloat162 h01 = __floats2bfloat162_rn(v.x, v.y);
    __nv_bfloat162 h23 = __floats2bfloat162_rn(v.z, v.w);
    uint2 hs; hs.x = *(uint32_t*)&h01; hs.y = *(uint32_t*)&h23;
    *(uint2*)&ah[m * DM + n4] = hs;
    float l0 = v.x - __bfloat162float(h01.x);
    float l1 = v.y - __bfloat162float(h01.y);
    float l2 = v.z - __bfloat162float(h23.x);
    float l3 = v.w - __bfloat162float(h23.y);
    uint2 q;
    q.x = e4m3x2(v.x, v.y) | (e4m3x2(l0 * 256.f, l1 * 256.f) << 16);
    q.y = e4m3x2(v.z, v.w) | (e4m3x2(l2 * 256.f, l3 * 256.f) << 16);
    *(uint2*)&aq[m * KQ + 2 * n4] = q;
}
__device__ __forceinline__ void emit_wt4(float4 v, size_t n, int k4,
                                         __nv_bfloat16* wh, uint8_t* wq) {
    __nv_bfloat162 h01 = __floats2bfloat162_rn(v.x, v.y);
    __nv_bfloat162 h23 = __floats2bfloat162_rn(v.z, v.w);
    uint2 hs; hs.x = *(uint32_t*)&h01; hs.y = *(uint32_t*)&h23;
    *(uint2*)&wh[n * DM + k4] = hs;
    float l0 = v.x - __bfloat162float(h01.x);
    float l1 = v.y - __bfloat162float(h01.y);
    float l2 = v.z - __bfloat162float(h23.x);
    float l3 = v.w - __bfloat162float(h23.y);
    uint2 q;
    q.x = e4m3x2(l0 * 256.f, l1 * 256.f) | (e4m3x2(v.x, v.y) << 16);
    q.y = e4m3x2(l2 * 256.f, l3 * 256.f) | (e4m3x2(v.z, v.w) << 16);
    *(uint2*)&wq[n * KQ + 2 * k4] = q;
}

// ---------------------------------------------------------------------------
// Shared GEMM geometry (R9-proven: 256 thr, 8 warps 64x32, regs=128, 2 CTA/SM)
// ---------------------------------------------------------------------------
#define STAGES 4
#define BK 32
#define PADK 40
#define STAGE_BYTES (2 * 128 * PADK * 2)
#define KITERS (DM / BK)

#define GEMM_PROLOG(ELT, AP, BP, KROW) \
    extern __shared__ __nv_bfloat16 sh[]; \
    const int bm = blockIdx.y * 128, bn = blockIdx.x * 128; \
    const int tid = threadIdx.x, lane = tid & 31, warp = tid >> 5; \
    const int wm = (warp >> 2) * 64, wn = (warp & 3) * 32; \
    uint32_t sbase = (uint32_t)__cvta_generic_to_shared(sh); \
    const int r0 = tid >> 2, seg = (tid & 3) * 8; \
    uint32_t dA0 = sbase + (r0 * PADK + seg) * 2; \
    uint32_t dA1 = sbase + ((r0 + 64) * PADK + seg) * 2; \
    uint32_t dB0 = sbase + (128 * PADK + r0 * PADK + seg) * 2; \
    uint32_t dB1 = dB0 + 64 * PADK * 2; \
    const ELT* gA0 = AP + (size_t)(bm + r0) * KROW + seg; \
    const ELT* gA1 = AP + (size_t)(bm + r0 + 64) * KROW + seg; \
    const ELT* gB0 = BP + (size_t)(bn + r0) * KROW + seg; \
    const ELT* gB1 = BP + (size_t)(bn + r0 + 64) * KROW + seg; \
    uint32_t aoff[4], boff[2]; \
    _Pragma("unroll") \
    for (int mi = 0; mi < 4; mi++) \
        aoff[mi] = ((wm + mi * 16 + (lane & 15)) * PADK + (lane >> 4) * 8) * 2; \
    _Pragma("unroll") \
    for (int nh = 0; nh < 2; nh++) \
        boff[nh] = (128 * PADK + (wn + nh * 16 + (lane >> 4) * 8 + (lane & 7)) * PADK \
                    + ((lane >> 3) & 1) * 8) * 2; \
    float acc[4][4][4] = {}; \
    auto load_stage = [&](int s) { \
        uint32_t so = (uint32_t)(s & (STAGES - 1)) * STAGE_BYTES; \
        int k0 = s * BK; \
        cp16(dA0 + so, gA0 + k0); \
        cp16(dA1 + so, gA1 + k0); \
        cp16(dB0 + so, gB0 + k0); \
        cp16(dB1 + so, gB1 + k0); \
    }; \
    load_stage(0); cp_commit(); \
    load_stage(1); cp_commit(); \
    load_stage(2); cp_commit();

#define GEMM_MAINLOOP(MMA) \
    for (int it = 0; it < KITERS; it++) { \
        cp_wait<2>(); \
        __syncthreads(); \
        uint32_t sb = sbase + (uint32_t)(it & (STAGES - 1)) * STAGE_BYTES; \
        if (it + 3 < KITERS) load_stage(it + 3); \
        cp_commit(); \
        _Pragma("unroll") \
        for (int ks = 0; ks < 2; ks++) { \
            uint32_t ko = sb + ks * 32; \
            uint32_t a[4][4], b[2][4]; \
            _Pragma("unroll") \
            for (int mi = 0; mi < 4; mi++) ldsm_x4(a[mi], ko + aoff[mi]); \
            _Pragma("unroll") \
            for (int nh = 0; nh < 2; nh++) ldsm_x4(b[nh], ko + boff[nh]); \
            _Pragma("unroll") \
            for (int mi = 0; mi < 4; mi++) \
                _Pragma("unroll") \
                for (int ni = 0; ni < 4; ni++) \
                    MMA(acc[mi][ni], a[mi], b[ni >> 1][(ni & 1) * 2], \
                        b[ni >> 1][(ni & 1) * 2 + 1]); \
        } \
    }

// ---------------------------------------------------------------------------
// bf16 main GEMM (NT): C = A * B^T + corr(bf16) + bias; z selects slot.
// ---------------------------------------------------------------------------
__global__ __launch_bounds__(256, 2) void gemm_bf16(
    const __nv_bfloat16* __restrict__ A, const __nv_bfloat16* __restrict__ Bbase,
    const float* __restrict__ bias0, const float* __restrict__ bias1,
    const __nv_bfloat16* __restrict__ corr0, const __nv_bfloat16* __restrict__ corr1,
    float* __restrict__ C0, float* __restrict__ C1)
{
    const int z = blockIdx.z;
    const __nv_bfloat16* B = Bbase + (size_t)z * DM * DM;
    const float* bias = z ? bias1 : bias0;
    const __nv_bfloat16* corr = z ? corr1 : corr0;
    float* C = z ? C1 : C0;

    GEMM_PROLOG(__nv_bfloat16, A, B, DM)
    GEMM_MAINLOOP(mma_bf16)

    const int er = lane >> 2, ec = (lane & 3) * 2;
    #pragma unroll
    for (int mi = 0; mi < 4; mi++) {
        int row = bm + wm + mi * 16 + er;
        #pragma unroll
        for (int ni = 0; ni < 4; ni++) {
            int col = bn + wn + ni * 8 + ec;
            float b0 = 0.f, b1 = 0.f;
            if (bias) { b0 = bias[col]; b1 = bias[col + 1]; }
            __nv_bfloat162 c0 = *(const __nv_bfloat162*)&corr[(size_t)row * DM + col];
            __nv_bfloat162 c1 = *(const __nv_bfloat162*)&corr[(size_t)(row + 8) * DM + col];
            float2 v;
            v.x = acc[mi][ni][0] + b0 + __bfloat162float(c0.x);
            v.y = acc[mi][ni][1] + b1 + __bfloat162float(c0.y);
            *(float2*)&C[(size_t)row * DM + col] = v;
            v.x = acc[mi][ni][2] + b0 + __bfloat162float(c1.x);
            v.y = acc[mi][ni][3] + b1 + __bfloat162float(c1.y);
            *(float2*)&C[(size_t)(row + 8) * DM + col] = v;
        }
    }
}

// ---------------------------------------------------------------------------
// bf16 GEMM with fused posty epilogue: y = acc + corr; v = y + BN(px)*Dv;
// g = gelu(v); emit packed act into set-2 buffers. (C matmul only.)
// ---------------------------------------------------------------------------
__global__ __launch_bounds__(256, 2) void gemm_bf16_posty(
    const __nv_bfloat16* __restrict__ A, const __nv_bfloat16* __restrict__ B,
    const __nv_bfloat16* __restrict__ corr,
    const float* __restrict__ x, const float* __restrict__ Dv,
    const float* __restrict__ w, const float* __restrict__ bb,
    __nv_bfloat16* __restrict__ ah, uint8_t* __restrict__ aq)
{
    GEMM_PROLOG(__nv_bfloat16, A, B, DM)
    GEMM_MAINLOOP(mma_bf16)

    const int er = lane >> 2, ec = (lane & 3) * 2;
    const float is2 = 0.70710678118654752f;
    #pragma unroll
    for (int mi = 0; mi < 4; mi++) {
        int row0 = bm + wm + mi * 16 + er;
        #pragma unroll
        for (int ni = 0; ni < 4; ni++) {
            int col = bn + wn + ni * 8 + ec;
            float2 mu = *(const float2*)&g_mean[col];
            float2 va = *(const float2*)&g_var[col];
            float2 wv = *(const float2*)&w[col];
            float2 bv = *(const float2*)&bb[col];
            float2 dv = *(const float2*)&Dv[col];
            float i0 = rsqrtf(va.x + BN_EPS) * wv.x;
            float i1 = rsqrtf(va.y + BN_EPS) * wv.y;
            #pragma unroll
            for (int h = 0; h < 2; h++) {
                int row = row0 + h * 8;
                float2 xv = *(const float2*)&x[(size_t)row * DM + col];
                __nv_bfloat162 cb = *(const __nv_bfloat162*)&corr[(size_t)row * DM + col];
                float y0 = acc[mi][ni][2 * h + 0] + __bfloat162float(cb.x);
                float y1 = acc[mi][ni][2 * h + 1] + __bfloat162float(cb.y);
                float v0 = y0 + ((xv.x - mu.x) * i0 + bv.x) * dv.x;
                float v1 = y1 + ((xv.y - mu.y) * i1 + bv.y) * dv.y;
                float g0 = 0.5f * v0 * (1.f + erff(v0 * is2));
                float g1 = 0.5f * v1 * (1.f + erff(v1 * is2));
                emit_act2(g0, g1, (size_t)row, col, ah, aq);
            }
        }
    }
}

// ---------------------------------------------------------------------------
// fp8 correction GEMM (NT): corr(bf16) = (A' * B'^T)/256; z selects slot.
// ---------------------------------------------------------------------------
__global__ __launch_bounds__(256, 2) void gemm_fp8(
    const uint16_t* __restrict__ A, const uint16_t* __restrict__ Bbase,
    __nv_bfloat16* __restrict__ C0, __nv_bfloat16* __restrict__ C1)
{
    const int z = blockIdx.z;
    const uint16_t* B = Bbase + (size_t)z * DM * KU;
    __nv_bfloat16* C = z ? C1 : C0;

    GEMM_PROLOG(uint16_t, A, B, KU)
    GEMM_MAINLOOP(mma_e4m3f)

    const float sc = 1.f / 256.f;
    const int er = lane >> 2, ec = (lane & 3) * 2;
    #pragma unroll
    for (int mi = 0; mi < 4; mi++) {
        int row = bm + wm + mi * 16 + er;
        #pragma unroll
        for (int ni = 0; ni < 4; ni++) {
            int col = bn + wn + ni * 8 + ec;
            __nv_bfloat162 v;
            v = __floats2bfloat162_rn(acc[mi][ni][0] * sc, acc[mi][ni][1] * sc);
            *(__nv_bfloat162*)&C[(size_t)row * DM + col] = v;
            v = __floats2bfloat162_rn(acc[mi][ni][2] * sc, acc[mi][ni][3] * sc);
            *(__nv_bfloat162*)&C[(size_t)(row + 8) * DM + col] = v;
        }
    }
}

// ---------------------------------------------------------------------------
// BatchNorm (two-phase stats, float4)
// ---------------------------------------------------------------------------
__global__ void bnp1(const float* __restrict__ x)
{
    const int c4 = blockIdx.x * 128 + (threadIdx.x & 31) * 4;
    const int r0 = threadIdx.x >> 5;
    const int t0 = blockIdx.y * 512;
    float4 s = {0,0,0,0}, ss = {0,0,0,0};
    for (int t = t0 + r0; t < t0 + 512; t += 8) {
        float4 v = *(const float4*)&x[(size_t)t * DM + c4];
        s.x += v.x; s.y += v.y; s.z += v.z; s.w += v.w;
        ss.x += v.x*v.x; ss.y += v.y*v.y; ss.z += v.z*v.z; ss.w += v.w*v.w;
    }
    __shared__ float4 sh_s[8][32], sh_ss[8][32];
    sh_s[r0][threadIdx.x & 31]  = s;
    sh_ss[r0][threadIdx.x & 31] = ss;
    __syncthreads();
    if (r0 == 0) {
        for (int r = 1; r < 8; r++) {
            float4 a = sh_s[r][threadIdx.x & 31], b = sh_ss[r][threadIdx.x & 31];
            s.x += a.x; s.y += a.y; s.z += a.z; s.w += a.w;
            ss.x += b.x; ss.y += b.y; ss.z += b.z; ss.w += b.w;
        }
        *(float4*)&g_bnp[blockIdx.y][0][c4] = s;
        *(float4*)&g_bnp[blockIdx.y][1][c4] = ss;
    }
}

__global__ void bnp2()
{
    int col = blockIdx.x * blockDim.x + threadIdx.x;
    float s = 0.f, ss = 0.f;
    #pragma unroll
    for (int r = 0; r < 8; r++) { s += g_bnp[r][0][col]; ss += g_bnp[r][1][col]; }
    float mu = s / (float)T_SEQ;
    g_mean[col] = mu;
    g_var[col]  = ss / (float)T_SEQ - mu * mu;
}

__global__ void bn_fuse(const float* __restrict__ x,
                        __nv_bfloat16* __restrict__ ah, uint8_t* __restrict__ aq,
                        const float* __restrict__ w, const float* __restrict__ b)
{
    int idx = blockIdx.x * blockDim.x + threadIdx.x;
    int n4 = (idx & (DM / 4 - 1)) * 4;
    size_t m = idx >> 9;
    float4 xv = *(const float4*)&x[m * DM + n4];
    float4 mu = *(const float4*)&g_mean[n4];
    float4 va = *(const float4*)&g_var[n4];
    float4 wv = *(const float4*)&w[n4];
    float4 bv = *(const float4*)&b[n4];
    float4 v;
    v.x = (xv.x - mu.x) * rsqrtf(va.x + BN_EPS) * wv.x + bv.x;
    v.y = (xv.y - mu.y) * rsqrtf(va.y + BN_EPS) * wv.y + bv.y;
    v.z = (xv.z - mu.z) * rsqrtf(va.z + BN_EPS) * wv.z + bv.z;
    v.w = (xv.w - mu.w) * rsqrtf(va.w + BN_EPS) * wv.w + bv.w;
    emit_act4(v, m, n4, ah, aq);
}

// ---------------------------------------------------------------------------
// Weight packing
// ---------------------------------------------------------------------------
__global__ void pack_w_plain(const float* __restrict__ W,
                             __nv_bfloat16* __restrict__ wh, uint8_t* __restrict__ wq)
{
    int idx = blockIdx.x * blockDim.x + threadIdx.x;
    size_t n = idx >> 9;
    int k4 = (idx & (DM / 4 - 1)) * 4;
    float4 v = *(const float4*)&W[n * DM + k4];
    emit_wt4(v, n, k4, wh, wq);
}

__global__ void pack_w_dual(const float* __restrict__ W1, const float* __restrict__ W2,
                            __nv_bfloat16* __restrict__ wh, uint8_t* __restrict__ wq)
{
    int idx = blockIdx.x * blockDim.x + threadIdx.x;
    size_t nn = idx >> 9;
    int slot = (nn >= DM);
    size_t n = nn & (DM - 1);
    int k4 = (idx & (DM / 4 - 1)) * 4;
    const float* W = slot ? W2 : W1;
    float4 v = *(const float4*)&W[n * DM + k4];
    emit_wt4(v, n, k4, wh + (size_t)slot * DM * DM, wq + (size_t)slot * DM * KQ);
}

__global__ void pack_Bn(const float* __restrict__ B_re, const float* __restrict__ B_im,
                        const float* __restrict__ gamma_log,
                        __nv_bfloat16* __restrict__ wh, uint8_t* __restrict__ wq)
{
    int idx = blockIdx.x * blockDim.x + threadIdx.x;
    size_t n = idx >> 9;
    int k4 = (idx & (DM / 4 - 1)) * 4;
    int jj = (int)n & (DH - 1);
    float g = expf(gamma_log[jj]);
    const float* src = (n < DH) ? B_re : B_im;
    float4 v = *(const float4*)&src[(size_t)jj * DM + k4];
    v.x *= g; v.y *= g; v.z *= g; v.w *= g;
    emit_wt4(v, n, k4, wh, wq);
}

__global__ void pack_Cc(const float* __restrict__ C_re, const float* __restrict__ C_im,
                        __nv_bfloat16* __restrict__ wh, uint8_t* __restrict__ wq)
{
    int idx = blockIdx.x * blockDim.x + threadIdx.x;
    size_t n = idx >> 9;
    int k4 = (idx & (DM / 4 - 1)) * 4;
    float4 v;
    if (k4 < DH) {
        v = *(const float4*)&C_re[n * DH + k4];
    } else {
        v = *(const float4*)&C_im[n * DH + (k4 - DH)];
        v.x = -v.x; v.y = -v.y; v.z = -v.z; v.w = -v.w;
    }
    emit_wt4(v, n, k4, wh, wq);
}

__global__ void pack_act_plain(const float* __restrict__ X,
                               __nv_bfloat16* __restrict__ ah, uint8_t* __restrict__ aq)
{
    int idx = blockIdx.x * blockDim.x + threadIdx.x;
    int n4 = (idx & (DM / 4 - 1)) * 4;
    size_t m = idx >> 9;
    float4 v = *(const float4*)&X[m * DM + n4];
    emit_act4(v, m, n4, ah, aq);
}

// ---------------------------------------------------------------------------
// LRU scan — chunk-parallel (3 passes)
// ---------------------------------------------------------------------------
__device__ __forceinline__ void lam_of(int j, const float* nu_log, const float* th_log,
                                       float& lr, float& li)
{
    float mag = expf(-expf(nu_log[j]));
    float ph  = expf(th_log[j]);
    lr = mag * cosf(ph);
    li = mag * sinf(ph);
}

__global__ void scan_p1(const float* __restrict__ Bu,
                        const float* __restrict__ nu_log, const float* __restrict__ th_log)
{
    int idx = blockIdx.x * blockDim.x + threadIdx.x;
    int j = (idx & (DH / 4 - 1)) * 4;
    int c = idx >> 8;
    float lr[4], li[4], hr[4] = {}, hi[4] = {};
    #pragma unroll
    for (int q = 0; q < 4; q++) lam_of(j + q, nu_log, th_log, lr[q], li[q]);
    int t0 = c * SCHL;
    for (int t = t0; t < t0 + SCHL; t++) {
        float4 br = *(const float4*)&Bu[(size_t)t * DM + j];
        float4 bi = *(const float4*)&Bu[(size_t)t * DM + DH + j];
        const float brr[4] = {br.x, br.y, br.z, br.w};
        const float bii[4] = {bi.x, bi.y, bi.z, bi.w};
        #pragma unroll
        for (int q = 0; q < 4; q++) {
            float nr = lr[q] * hr[q] - li[q] * hi[q] + brr[q];
            float ni = lr[q] * hi[q] + li[q] * hr[q] + bii[q];
            hr[q] = nr; hi[q] = ni;
        }
    }
    *(float4*)&g_carr[c * DH + j] = make_float4(hr[0], hr[1], hr[2], hr[3]);
    *(float4*)&g_cari[c * DH + j] = make_float4(hi[0], hi[1], hi[2], hi[3]);
}

__global__ void scan_fix(const float* __restrict__ nu_log, const float* __restrict__ th_log)
{
    int j = blockIdx.x * blockDim.x + threadIdx.x;
    float lr, li; lam_of(j, nu_log, th_log, lr, li);
    float ar = lr, ai = li;
    #pragma unroll
    for (int s = 0; s < 6; s++) {
        float nr = ar * ar - ai * ai;
        float ni = 2.f * ar * ai;
        ar = nr; ai = ni;
    }
    float cr = 0.f, ci = 0.f;
    for (int c = 0; c < SCH; c++) {
        g_cinr[c * DH + j] = cr;
        g_cini[c * DH + j] = ci;
        float nr = ar * cr - ai * ci + g_carr[c * DH + j];
        float ni = ar * ci + ai * cr + g_cari[c * DH + j];
        cr = nr; ci = ni;
    }
}

__global__ void scan_p2(const float* __restrict__ Bu,
                        __nv_bfloat16* __restrict__ ah, uint8_t* __restrict__ aq,
                        const float* __restrict__ nu_log, const float* __restrict__ th_log)
{
    int idx = blockIdx.x * blockDim.x + threadIdx.x;
    int j = (idx & (DH / 4 - 1)) * 4;
    int c = idx >> 8;
    float lr[4], li[4], hr[4], hi[4];
    #pragma unroll
    for (int q = 0; q < 4; q++) {
        lam_of(j + q, nu_log, th_log, lr[q], li[q]);
        hr[q] = g_cinr[c * DH + j + q];
        hi[q] = g_cini[c * DH + j + q];
    }
    int t0 = c * SCHL;
    for (int t = t0; t < t0 + SCHL; t++) {
        float4 br = *(const float4*)&Bu[(size_t)t * DM + j];
        float4 bi = *(const float4*)&Bu[(size_t)t * DM + DH + j];
        const float brr[4] = {br.x, br.y, br.z, br.w};
        const float bii[4] = {bi.x, bi.y, bi.z, bi.w};
        #pragma unroll
        for (int q = 0; q < 4; q++) {
            float nr = lr[q] * hr[q] - li[q] * hi[q] + brr[q];
            float ni = lr[q] * hi[q] + li[q] * hr[q] + bii[q];
            hr[q] = nr; hi[q] = ni;
        }
        emit_act4(make_float4(hr[0], hr[1], hr[2], hr[3]), (size_t)t, j, ah, aq);
        emit_act4(make_float4(hi[0], hi[1], hi[2], hi[3]), (size_t)t, DH + j, ah, aq);
    }
}

// ---------------------------------------------------------------------------
// GLU combine
// ---------------------------------------------------------------------------
__global__ void glu_combine(const float* __restrict__ x, const float* __restrict__ u,
                            const float* __restrict__ v, float* __restrict__ out)
{
    int idx = blockIdx.x * blockDim.x + threadIdx.x;
    float4 xv = *(const float4*)&x[(size_t)idx * 4];
    float4 uv = *(const float4*)&u[(size_t)idx * 4];
    float4 vv = *(const float4*)&v[(size_t)idx * 4];
    float4 o;
    o.x = xv.x + uv.x / (1.f + expf(-vv.x));
    o.y = xv.y + uv.y / (1.f + expf(-vv.y));
    o.z = xv.z + uv.z / (1.f + expf(-vv.z));
    o.w = xv.w + uv.w / (1.f + expf(-vv.w));
    *(float4*)&out[(size_t)idx * 4] = o;
}

// ---------------------------------------------------------------------------
// Launch
// ---------------------------------------------------------------------------
extern "C" void kernel_launch(void* const* d_in, const int* in_sizes, int n_in,
                              void* d_out, int out_size)
{
    const float* x_in      = (const float*)d_in[0];
    const float* enc_w     = (const float*)d_in[1];
    const float* enc_b     = (const float*)d_in[2];
    const float* nu_log    = (const float*)d_in[3];
    const float* theta_log = (const float*)d_in[4];
    const float* gamma_log = (const float*)d_in[5];
    const float* B_re      = (const float*)d_in[6];
    const float* B_im      = (const float*)d_in[7];
    const float* C_re      = (const float*)d_in[8];
    const float* C_im      = (const float*)d_in[9];
    const float* Dv        = (const float*)d_in[10];
    const float* norm_w    = (const float*)d_in[11];
    const float* norm_b    = (const float*)d_in[12];
    const float* out1_w    = (const float*)d_in[13];
    const float* out1_b    = (const float*)d_in[14];
    const float* out2_w    = (const float*)d_in[15];
    const float* out2_b    = (const float*)d_in[16];
    float* out = (float*)d_out;
    (void)in_sizes; (void)n_in; (void)out_size;

    float *px, *pt1, *pu, *pv;
    __nv_bfloat16 *pcorr, *pcorr2, *pah, *pah2, *pwh;
    uint8_t *paq, *paq2, *pwq;
    cudaGetSymbolAddress((void**)&px,     g_x);
    cudaGetSymbolAddress((void**)&pt1,    g_t1);
    cudaGetSymbolAddress((void**)&pu,     g_u);
    cudaGetSymbolAddress((void**)&pv,     g_v);
    cudaGetSymbolAddress((void**)&pcorr,  g_corr);
    cudaGetSymbolAddress((void**)&pcorr2, g_corr2);
    cudaGetSymbolAddress((void**)&pah,    g_ah);
    cudaGetSymbolAddress((void**)&paq,    g_aq);
    cudaGetSymbolAddress((void**)&pah2,   g_ah2);
    cudaGetSymbolAddress((void**)&paq2,   g_aq2);
    cudaGetSymbolAddress((void**)&pwh,    g_wh);
    cudaGetSymbolAddress((void**)&pwq,    g_wq);

    const int SMEM = STAGES * STAGE_BYTES;
    cudaFuncSetAttribute(gemm_bf16, cudaFuncAttributeMaxDynamicSharedMemorySize, SMEM);
    cudaFuncSetAttribute(gemm_bf16_posty, cudaFuncAttributeMaxDynamicSharedMemorySize, SMEM);
    cudaFuncSetAttribute(gemm_fp8,  cudaFuncAttributeMaxDynamicSharedMemorySize, SMEM);

    dim3 ggrid (DM / 128, T_SEQ / 128, 1);
    dim3 ggrid2(DM / 128, T_SEQ / 128, 2);
    const int EW4 = (T_SEQ * DM) / (4 * 256);
    const int PW4 = (DM * DM) / (4 * 256);
    dim3 bgrid(DM / 128, 8);
    const int SCB = (SCH * DH / 4) / 256;
    const uint16_t* paq16  = (const uint16_t*)paq;
    const uint16_t* paq216 = (const uint16_t*)paq2;
    const uint16_t* pwq16  = (const uint16_t*)pwq;

    // Encoder
    pack_act_plain<<<EW4, 256>>>(x_in, pah, paq);
    pack_w_plain<<<PW4, 256>>>(enc_w, pwh, pwq);
    gemm_fp8<<<ggrid, 256, SMEM>>>(paq16, pwq16, pcorr, pcorr);
    gemm_bf16<<<ggrid, 256, SMEM>>>(pah, pwh, enc_b, enc_b, pcorr, pcorr, px, px);

    for (int l = 0; l < L_LAYERS; l++) {
        const float* nw  = norm_w + l * DM;
        const float* nb  = norm_b + l * DM;
        const float* nu  = nu_log + l * DH;
        const float* th  = theta_log + l * DH;
        const float* gl  = gamma_log + l * DH;
        const float* bre = B_re + (size_t)l * DH * DM;
        const float* bim = B_im + (size_t)l * DH * DM;
        const float* cre = C_re + (size_t)l * DM * DH;
        const float* cim = C_im + (size_t)l * DM * DH;
        const float* dv  = Dv + l * DM;
        const float* w1  = out1_w + (size_t)l * DM * DM;
        const float* b1  = out1_b + l * DM;
        const float* w2  = out2_w + (size_t)l * DM * DM;
        const float* b2  = out2_b + l * DM;

        bnp1<<<bgrid, 256>>>(px);
        bnp2<<<DM / 256, 256>>>();
        bn_fuse<<<EW4, 256>>>(px, pah, paq, nw, nb);

        pack_Bn<<<PW4, 256>>>(bre, bim, gl, pwh, pwq);
        gemm_fp8<<<ggrid, 256, SMEM>>>(paq16, pwq16, pcorr, pcorr);
        gemm_bf16<<<ggrid, 256, SMEM>>>(pah, pwh, nullptr, nullptr, pcorr, pcorr, pt1, pt1);

        scan_p1<<<SCB, 256>>>(pt1, nu, th);
        scan_fix<<<DH / 256, 256>>>(nu, th);
        scan_p2<<<SCB, 256>>>(pt1, pah, paq, nu, th);

        pack_Cc<<<PW4, 256>>>(cre, cim, pwh, pwq);
        gemm_fp8<<<ggrid, 256, SMEM>>>(paq16, pwq16, pcorr, pcorr);
        gemm_bf16_posty<<<ggrid, 256, SMEM>>>(pah, pwh, pcorr, px, dv, nw, nb, pah2, paq2);

        pack_w_dual<<<2 * PW4, 256>>>(w1, w2, pwh, pwq);
        gemm_fp8<<<ggrid2, 256, SMEM>>>(paq216, pwq16, pcorr, pcorr2);
        gemm_bf16<<<ggrid2, 256, SMEM>>>(pah2, pwh, b1, b2, pcorr, pcorr2, pu, pv);

        float* dst = (l == L_LAYERS - 1) ? out : px;
        glu_combine<<<EW4, 256>>>(px, pu, pv, dst);
    }
}